// round 14
// baseline (speedup 1.0000x reference)
#include <cuda_runtime.h>
#include <cstdint>

// BallPointQuery: per centroid, indices of up to 64 points within RADIUS
// (ascending), padded with first-neighbor index (0 if none).
// B=8, N=16384, M=1024, K=64. Output dtype: FLOAT32 (indices as floats).
//
// Round 14: trade ILP for TLP. R13's ping-pong prefetch cost ~48 live regs
// (80 total) -> only 24 warps/SM (occ 30%, issue 49%). Drop the prefetch;
// ~48-56 regs -> ~40 warps/SM. TLP hides the per-chunk L1 latency better
// than 1-deep ILP, and early-exit no longer wastes a prefetched chunk.
// Kept: f32x2 packed math on double2 pairs (zero marshal), shfl-scan slot
// assignment, sparse ffs write loop, warp work stealing, eps-band +-1e-5
// around r2=0.04 with exact expanded-formula fallback.
// => hit decisions unchanged: rel_err must remain exactly 4.700719e-4.

#define BB 8
#define NN 16384
#define MM 1024
#define KSAMP 64
#define TOTAL_WARPS (BB * MM)

typedef unsigned long long ull;

#define ADDX2(out, a, b) \
    asm("add.rn.f32x2 %0, %1, %2;" : "=l"(out) : "l"(a), "l"(b))
#define MULX2(out, a, b) \
    asm("mul.rn.f32x2 %0, %1, %2;" : "=l"(out) : "l"(a), "l"(b))
#define FMAX2(out, a, b, c) \
    asm("fma.rn.f32x2 %0, %1, %2, %3;" : "=l"(out) : "l"(a), "l"(b), "l"(c))

__device__ unsigned g_ctr;

__global__ void reset_ctr_kernel() { g_ctr = 0u; }

__device__ __forceinline__ float lo_f(ull v) {
    return __uint_as_float((unsigned)v);
}
__device__ __forceinline__ float hi_f(ull v) {
    return __uint_as_float((unsigned)(v >> 32));
}

__device__ __forceinline__ float exact_d2(float c2, float cx, float cy, float cz,
                                          float x, float y, float z)
{
    float p2 = __fadd_rn(__fadd_rn(__fmul_rn(x, x), __fmul_rn(y, y)),
                         __fmul_rn(z, z));
    float cp = __fadd_rn(__fadd_rn(__fmul_rn(cx, x), __fmul_rn(cy, y)),
                         __fmul_rn(cz, z));
    return __fsub_rn(__fadd_rn(c2, p2), __fmul_rn(2.0f, cp));
}

__global__ void __launch_bounds__(128)
ballquery_kernel(const float* __restrict__ pts,    // [8, 3, 16384]
                 const float* __restrict__ cent,   // [8, 3, 1024]
                 float* __restrict__ out)          // [8, 1024, 64] f32
{
    const unsigned FULL = 0xffffffffu;
    int lane = (int)(threadIdx.x & 31);

    const float r2   = 0.04f;
    const float R2LO = 0.04f - 1e-5f;
    const float R2HI = 0.04f + 1e-5f;

    for (;;) {
        unsigned widx;
        if (lane == 0) widx = atomicAdd(&g_ctr, 1u);
        widx = __shfl_sync(FULL, widx, 0);
        if (widx >= TOTAL_WARPS) return;

        int b = (int)(widx >> 10);
        int m = (int)(widx & (MM - 1));

        const float* px = pts + (size_t)b * 3 * NN;   // y at +NN, z at +2*NN
        const float* cb = cent + (size_t)b * 3 * MM;

        float cx = __ldg(cb + m);
        float cy = __ldg(cb + MM + m);
        float cz = __ldg(cb + 2 * MM + m);

        float c2 = __fadd_rn(__fadd_rn(__fmul_rn(cx, cx), __fmul_rn(cy, cy)),
                             __fmul_rn(cz, cz));

        ull ncx2, ncy2, ncz2;   // packed (-c, -c)
        {
            unsigned nx = __float_as_uint(-cx);
            unsigned ny = __float_as_uint(-cy);
            unsigned nz = __float_as_uint(-cz);
            ncx2 = ((ull)nx << 32) | nx;
            ncy2 = ((ull)ny << 32) | ny;
            ncz2 = ((ull)nz << 32) | nz;
        }

        float* __restrict__ row = out + (size_t)widx * KSAMP;

        int base = 0;
        int first_idx = -1;
        const int nl = 8 * lane;

        for (int n0 = 0; n0 < NN; n0 += 256) {
            const float* p0 = px + n0 + nl;
            ull Xp[4], Yp[4], Zp[4];
            {
                double2 v;
                v = __ldg((const double2*)(p0));
                Xp[0] = __double_as_longlong(v.x); Xp[1] = __double_as_longlong(v.y);
                v = __ldg((const double2*)(p0 + 4));
                Xp[2] = __double_as_longlong(v.x); Xp[3] = __double_as_longlong(v.y);
                v = __ldg((const double2*)(p0 + NN));
                Yp[0] = __double_as_longlong(v.x); Yp[1] = __double_as_longlong(v.y);
                v = __ldg((const double2*)(p0 + NN + 4));
                Yp[2] = __double_as_longlong(v.x); Yp[3] = __double_as_longlong(v.y);
                v = __ldg((const double2*)(p0 + 2 * NN));
                Zp[0] = __double_as_longlong(v.x); Zp[1] = __double_as_longlong(v.y);
                v = __ldg((const double2*)(p0 + 2 * NN + 4));
                Zp[2] = __double_as_longlong(v.x); Zp[3] = __double_as_longlong(v.y);
            }

            unsigned h = 0, band = 0;
            #pragma unroll
            for (int p = 0; p < 4; p++) {
                ull dx, dy, dz, s;
                ADDX2(dx, Xp[p], ncx2);
                ADDX2(dy, Yp[p], ncy2);
                ADDX2(dz, Zp[p], ncz2);
                MULX2(s, dx, dx);
                FMAX2(s, dy, dy, s);
                FMAX2(s, dz, dz, s);
                float d0 = lo_f(s), d1 = hi_f(s);
                if (d0 <= R2HI) { if (d0 <= R2LO) h |= 1u << (2*p);   else band |= 1u << (2*p); }
                if (d1 <= R2HI) { if (d1 <= R2LO) h |= 1u << (2*p+1); else band |= 1u << (2*p+1); }
            }

            // Rare borderline points: exact expanded formula decides.
            if (__ballot_sync(FULL, band != 0u)) {
                #pragma unroll
                for (int j = 0; j < 8; j++) {
                    if (band & (1u << j)) {
                        float x = (j & 1) ? hi_f(Xp[j >> 1]) : lo_f(Xp[j >> 1]);
                        float y = (j & 1) ? hi_f(Yp[j >> 1]) : lo_f(Yp[j >> 1]);
                        float z = (j & 1) ? hi_f(Zp[j >> 1]) : lo_f(Zp[j >> 1]);
                        if (exact_d2(c2, cx, cy, cz, x, y, z) <= r2)
                            h |= (1u << j);
                    }
                }
            }

            unsigned hb = __ballot_sync(FULL, h != 0u);
            if (!hb) continue;                  // warp-uniform: empty chunk

            if (first_idx < 0) {
                int l0 = __ffs(hb) - 1;
                unsigned h0 = __shfl_sync(FULL, h, l0);
                first_idx = n0 + 8 * l0 + (__ffs(h0) - 1);
            }

            // Inclusive shfl scan of per-lane counts (lane-major order).
            int cnt = __popc(h);
            int inc = cnt;
            #pragma unroll
            for (int off = 1; off < 32; off <<= 1) {
                int v = __shfl_up_sync(FULL, inc, off);
                if (lane >= off) inc += v;
            }
            int total = __shfl_sync(FULL, inc, 31);
            int myPos = base + inc - cnt;

            // Sparse write: one iteration per actual hit in this lane.
            int base_n = n0 + nl;
            unsigned hh = h;
            while (hh) {
                int j = __ffs(hh) - 1;
                hh &= hh - 1;
                if (myPos < KSAMP)
                    row[myPos] = (float)(base_n + j);
                myPos++;
            }
            base += total;
            if (base >= KSAMP) break;           // warp-uniform
        }

        int cnt = base < KSAMP ? base : KSAMP;
        if (first_idx < 0) first_idx = 0;
        float pad = (float)first_idx;
        for (int s = cnt + lane; s < KSAMP; s += 32)
            row[s] = pad;
    }
}

extern "C" void kernel_launch(void* const* d_in, const int* in_sizes, int n_in,
                              void* d_out, int out_size)
{
    // points = largest input, centroids = smallest (robust binding).
    int ip = 0, ic = 0;
    for (int i = 1; i < n_in; i++) {
        if (in_sizes[i] > in_sizes[ip]) ip = i;
        if (in_sizes[i] < in_sizes[ic]) ic = i;
    }
    if (ip == ic && n_in >= 2) { ip = 0; ic = 1; }

    const float* pts  = (const float*)d_in[ip];
    const float* cent = (const float*)d_in[ic];
    float* out = (float*)d_out;

    reset_ctr_kernel<<<1, 1>>>();

    // Fill residency: ~10 blocks/SM at <=56 regs -> 1480 blocks x 4 warps
    // stealing 8192 centroids.
    const int threads = 128;
    const int blocks  = 1480;
    ballquery_kernel<<<blocks, threads>>>(pts, cent, out);
}

// round 15
// speedup vs baseline: 1.1148x; 1.1148x over previous
#include <cuda_runtime.h>
#include <cstdint>

// BallPointQuery: per centroid, indices of up to 64 points within RADIUS
// (ascending), padded with first-neighbor index (0 if none).
// B=8, N=16384, M=1024, K=64. Output dtype: FLOAT32 (indices as floats).
//
// Round 15 (= R13 best config + two fixes):
//  - bit-sliced ballot prefix (4 parallel ballots over bits of popc(h))
//    replaces the 5-serial-shfl scan: same inst count, ~1 ballot critical
//    path instead of ~130 cycles
//  - resident-sized persistent grid (888 blocks = 6/SM @ 80 regs): no
//    second block wave; work stealing handles balance
//  - kept from R13: 256-pt chunks, ping-pong double-buffer prefetch,
//    f32x2 packed math on double2 pairs, sparse ffs write loop, warp work
//    stealing, eps-band +-1e-5 around r2=0.04 with exact expanded-formula
//    fallback
//  => hit decisions unchanged: rel_err must remain exactly 4.700719e-4.

#define BB 8
#define NN 16384
#define MM 1024
#define KSAMP 64
#define TOTAL_WARPS (BB * MM)

typedef unsigned long long ull;

#define ADDX2(out, a, b) \
    asm("add.rn.f32x2 %0, %1, %2;" : "=l"(out) : "l"(a), "l"(b))
#define MULX2(out, a, b) \
    asm("mul.rn.f32x2 %0, %1, %2;" : "=l"(out) : "l"(a), "l"(b))
#define FMAX2(out, a, b, c) \
    asm("fma.rn.f32x2 %0, %1, %2, %3;" : "=l"(out) : "l"(a), "l"(b), "l"(c))

__device__ unsigned g_ctr;

__global__ void reset_ctr_kernel() { g_ctr = 0u; }

__device__ __forceinline__ float lo_f(ull v) {
    return __uint_as_float((unsigned)v);
}
__device__ __forceinline__ float hi_f(ull v) {
    return __uint_as_float((unsigned)(v >> 32));
}

__device__ __forceinline__ float exact_d2(float c2, float cx, float cy, float cz,
                                          float x, float y, float z)
{
    float p2 = __fadd_rn(__fadd_rn(__fmul_rn(x, x), __fmul_rn(y, y)),
                         __fmul_rn(z, z));
    float cp = __fadd_rn(__fadd_rn(__fmul_rn(cx, x), __fmul_rn(cy, y)),
                         __fmul_rn(cz, z));
    return __fsub_rn(__fadd_rn(c2, p2), __fmul_rn(2.0f, cp));
}

__global__ void __launch_bounds__(128)
ballquery_kernel(const float* __restrict__ pts,    // [8, 3, 16384]
                 const float* __restrict__ cent,   // [8, 3, 1024]
                 float* __restrict__ out)          // [8, 1024, 64] f32
{
    const unsigned FULL = 0xffffffffu;
    int lane = (int)(threadIdx.x & 31);

    const float r2   = 0.04f;
    const float R2LO = 0.04f - 1e-5f;
    const float R2HI = 0.04f + 1e-5f;
    const unsigned below = (1u << lane) - 1u;

    for (;;) {
        unsigned widx;
        if (lane == 0) widx = atomicAdd(&g_ctr, 1u);
        widx = __shfl_sync(FULL, widx, 0);
        if (widx >= TOTAL_WARPS) return;

        int b = (int)(widx >> 10);
        int m = (int)(widx & (MM - 1));

        const float* px = pts + (size_t)b * 3 * NN;   // y at +NN, z at +2*NN
        const float* cb = cent + (size_t)b * 3 * MM;

        float cx = __ldg(cb + m);
        float cy = __ldg(cb + MM + m);
        float cz = __ldg(cb + 2 * MM + m);

        float c2 = __fadd_rn(__fadd_rn(__fmul_rn(cx, cx), __fmul_rn(cy, cy)),
                             __fmul_rn(cz, cz));

        ull ncx2, ncy2, ncz2;   // packed (-c, -c)
        {
            unsigned nx = __float_as_uint(-cx);
            unsigned ny = __float_as_uint(-cy);
            unsigned nz = __float_as_uint(-cz);
            ncx2 = ((ull)nx << 32) | nx;
            ncy2 = ((ull)ny << 32) | ny;
            ncz2 = ((ull)nz << 32) | nz;
        }

        float* __restrict__ row = out + (size_t)widx * KSAMP;

        int base = 0;
        int first_idx = -1;
        const int nl = 8 * lane;

        // Process one 256-point chunk; returns true when 64 hits reached.
        auto chunk = [&](int n0, double2 X0, double2 X1, double2 Y0,
                         double2 Y1, double2 Z0, double2 Z1) -> bool {
            ull Xp[4] = { __double_as_longlong(X0.x), __double_as_longlong(X0.y),
                          __double_as_longlong(X1.x), __double_as_longlong(X1.y) };
            ull Yp[4] = { __double_as_longlong(Y0.x), __double_as_longlong(Y0.y),
                          __double_as_longlong(Y1.x), __double_as_longlong(Y1.y) };
            ull Zp[4] = { __double_as_longlong(Z0.x), __double_as_longlong(Z0.y),
                          __double_as_longlong(Z1.x), __double_as_longlong(Z1.y) };

            unsigned h = 0, band = 0;
            #pragma unroll
            for (int p = 0; p < 4; p++) {
                ull dx, dy, dz, s;
                ADDX2(dx, Xp[p], ncx2);
                ADDX2(dy, Yp[p], ncy2);
                ADDX2(dz, Zp[p], ncz2);
                MULX2(s, dx, dx);
                FMAX2(s, dy, dy, s);
                FMAX2(s, dz, dz, s);
                float d0 = lo_f(s), d1 = hi_f(s);
                if (d0 <= R2HI) { if (d0 <= R2LO) h |= 1u << (2*p);   else band |= 1u << (2*p); }
                if (d1 <= R2HI) { if (d1 <= R2LO) h |= 1u << (2*p+1); else band |= 1u << (2*p+1); }
            }

            // Rare borderline points: exact expanded formula decides.
            if (__ballot_sync(FULL, band != 0u)) {
                #pragma unroll
                for (int j = 0; j < 8; j++) {
                    if (band & (1u << j)) {
                        float x = (j & 1) ? hi_f(Xp[j >> 1]) : lo_f(Xp[j >> 1]);
                        float y = (j & 1) ? hi_f(Yp[j >> 1]) : lo_f(Yp[j >> 1]);
                        float z = (j & 1) ? hi_f(Zp[j >> 1]) : lo_f(Zp[j >> 1]);
                        if (exact_d2(c2, cx, cy, cz, x, y, z) <= r2)
                            h |= (1u << j);
                    }
                }
            }

            unsigned hb = __ballot_sync(FULL, h != 0u);
            if (!hb) return false;              // warp-uniform: empty chunk

            if (first_idx < 0) {
                int l0 = __ffs(hb) - 1;
                unsigned h0 = __shfl_sync(FULL, h, l0);
                first_idx = n0 + 8 * l0 + (__ffs(h0) - 1);
            }

            // Bit-sliced ballot prefix over per-lane counts (0..8):
            // all ballots independent -> ~1 ballot critical path.
            int cnt = __popc(h);
            unsigned q0 = __ballot_sync(FULL, cnt & 1);
            unsigned q1 = __ballot_sync(FULL, cnt & 2);
            unsigned q2 = __ballot_sync(FULL, cnt & 4);
            unsigned q3 = __ballot_sync(FULL, cnt & 8);
            int myPos = base
                      + __popc(q0 & below)
                      + 2 * __popc(q1 & below)
                      + 4 * __popc(q2 & below)
                      + 8 * __popc(q3 & below);
            int total = __popc(q0) + 2 * __popc(q1)
                      + 4 * __popc(q2) + 8 * __popc(q3);

            // Sparse write: one iteration per actual hit in this lane.
            int base_n = n0 + nl;
            unsigned hh = h;
            while (hh) {
                int j = __ffs(hh) - 1;
                hh &= hh - 1;
                if (myPos < KSAMP)
                    row[myPos] = (float)(base_n + j);
                myPos++;
            }
            base += total;
            return base >= KSAMP;               // warp-uniform
        };

        // Ping-pong double-buffered scan (64 chunks; even count).
        double2 AX0 = __ldg((const double2*)(px + nl));
        double2 AX1 = __ldg((const double2*)(px + nl + 4));
        double2 AY0 = __ldg((const double2*)(px + NN + nl));
        double2 AY1 = __ldg((const double2*)(px + NN + nl + 4));
        double2 AZ0 = __ldg((const double2*)(px + 2 * NN + nl));
        double2 AZ1 = __ldg((const double2*)(px + 2 * NN + nl + 4));
        double2 BX0, BX1, BY0, BY1, BZ0, BZ1;

        for (int n0 = 0;;) {
            bool more = (n0 + 256) < NN;
            if (more) {
                int nn = n0 + 256 + nl;
                BX0 = __ldg((const double2*)(px + nn));
                BX1 = __ldg((const double2*)(px + nn + 4));
                BY0 = __ldg((const double2*)(px + NN + nn));
                BY1 = __ldg((const double2*)(px + NN + nn + 4));
                BZ0 = __ldg((const double2*)(px + 2 * NN + nn));
                BZ1 = __ldg((const double2*)(px + 2 * NN + nn + 4));
            }
            if (chunk(n0, AX0, AX1, AY0, AY1, AZ0, AZ1) || !more) break;
            n0 += 256;

            bool more2 = (n0 + 256) < NN;
            if (more2) {
                int nn = n0 + 256 + nl;
                AX0 = __ldg((const double2*)(px + nn));
                AX1 = __ldg((const double2*)(px + nn + 4));
                AY0 = __ldg((const double2*)(px + NN + nn));
                AY1 = __ldg((const double2*)(px + NN + nn + 4));
                AZ0 = __ldg((const double2*)(px + 2 * NN + nn));
                AZ1 = __ldg((const double2*)(px + 2 * NN + nn + 4));
            }
            if (chunk(n0, BX0, BX1, BY0, BY1, BZ0, BZ1) || !more2) break;
            n0 += 256;
        }

        int cnt = base < KSAMP ? base : KSAMP;
        if (first_idx < 0) first_idx = 0;
        float pad = (float)first_idx;
        for (int s = cnt + lane; s < KSAMP; s += 32)
            row[s] = pad;
    }
}

extern "C" void kernel_launch(void* const* d_in, const int* in_sizes, int n_in,
                              void* d_out, int out_size)
{
    // points = largest input, centroids = smallest (robust binding).
    int ip = 0, ic = 0;
    for (int i = 1; i < n_in; i++) {
        if (in_sizes[i] > in_sizes[ip]) ip = i;
        if (in_sizes[i] < in_sizes[ic]) ic = i;
    }
    if (ip == ic && n_in >= 2) { ip = 0; ic = 1; }

    const float* pts  = (const float*)d_in[ip];
    const float* cent = (const float*)d_in[ic];
    float* out = (float*)d_out;

    reset_ctr_kernel<<<1, 1>>>();

    // Resident-sized persistent grid: 6 blocks/SM @ 80 regs x 148 SMs.
    const int threads = 128;
    const int blocks  = 888;
    ballquery_kernel<<<blocks, threads>>>(pts, cent, out);
}